// round 4
// baseline (speedup 1.0000x reference)
#include <cuda_runtime.h>
#include <cstdint>

// Inputs (bound by element count, not position):
//   x       float32 [1000000, 2]        -> 2,000,000 elems
//   phases  float32 [16000000]          -> 16,000,000 elems
//   edges   int64-or-int32 [16000000,2] -> 32,000,000 elems
// Output: float32 [1000000, 2]

static constexpr int N_NODES = 1000000;
static constexpr int N_EDGES = 16000000;

// ---------------------------------------------------------------------------
// out = x (out arrives poisoned).
// ---------------------------------------------------------------------------
__global__ void init_out_kernel(const float4* __restrict__ x4,
                                float4* __restrict__ out4,
                                int n4) {
    int i = blockIdx.x * blockDim.x + threadIdx.x;
    if (i < n4) out4[i] = x4[i];
}

// ---------------------------------------------------------------------------
// Streaming loads: evict-first (.cs) to keep x/out hot in L2.
// ---------------------------------------------------------------------------
__device__ __forceinline__ int4 ldg_cs_int4(const int4* p) {
    int4 r;
    asm volatile("ld.global.cs.v4.s32 {%0,%1,%2,%3}, [%4];"
                 : "=r"(r.x), "=r"(r.y), "=r"(r.z), "=r"(r.w) : "l"(p));
    return r;
}
__device__ __forceinline__ float4 ldg_cs_float4(const float4* p) {
    float4 r;
    asm volatile("ld.global.cs.v4.f32 {%0,%1,%2,%3}, [%4];"
                 : "=f"(r.x), "=f"(r.y), "=f"(r.z), "=f"(r.w) : "l"(p));
    return r;
}
__device__ __forceinline__ longlong2 ldg_cs_ll2(const longlong2* p) {
    longlong2 r;
    asm volatile("ld.global.cs.v2.s64 {%0,%1}, [%2];"
                 : "=l"(r.x), "=l"(r.y) : "l"(p));
    return r;
}

__device__ __forceinline__ void red_v2(float* dst, float a, float b) {
    asm volatile("red.global.add.v2.f32 [%0], {%1, %2};"
                 :: "l"(dst), "f"(a), "f"(b) : "memory");
}

// ---------------------------------------------------------------------------
// 4 edges per thread. Phase loads as float4, edges as 2x int4 (int32 path)
// or 4x v2.s64 (int64 path). All 8 gathers are issued before any reduction
// (MLP=8), then 8 independent red.global.add.v2.f32.
// ---------------------------------------------------------------------------
__global__ void __launch_bounds__(256)
edge_scatter_kernel(const float2* __restrict__ x,
                    const float* __restrict__ phases,
                    const void* __restrict__ edges_raw,
                    float* __restrict__ out) {
    __shared__ int s_mode;  // 1 = int32 pairs, 2 = int64 pairs
    if (threadIdx.x == 0) {
        const long long* e64 = (const long long*)edges_raw;
        int mode = 2;
        #pragma unroll
        for (int i = 1; i < 9; i += 2) {
            long long val = __ldg(&e64[i]);
            if (val < 0 || val >= (long long)N_NODES) { mode = 1; break; }
        }
        s_mode = mode;
    }
    __syncthreads();
    int mode = s_mode;

    int gid = blockIdx.x * blockDim.x + threadIdx.x;   // [0, N_EDGES/4)
    if (gid >= N_EDGES / 4) return;

    float4 ph = ldg_cs_float4(((const float4*)phases) + gid);
    float s0, c0, s1, c1, s2, c2, s3, c3;
    __sincosf(ph.x, &s0, &c0);
    __sincosf(ph.y, &s1, &c1);
    __sincosf(ph.z, &s2, &c2);
    __sincosf(ph.w, &s3, &c3);

    int u0, v0, u1, v1, u2, v2, u3, v3;
    if (mode == 1) {
        int4 ea = ldg_cs_int4(((const int4*)edges_raw) + 2 * gid);
        int4 eb = ldg_cs_int4(((const int4*)edges_raw) + 2 * gid + 1);
        u0 = ea.x; v0 = ea.y; u1 = ea.z; v1 = ea.w;
        u2 = eb.x; v2 = eb.y; u3 = eb.z; v3 = eb.w;
    } else {
        const longlong2* e2 = ((const longlong2*)edges_raw) + 4 * gid;
        longlong2 a = ldg_cs_ll2(e2);
        longlong2 b = ldg_cs_ll2(e2 + 1);
        longlong2 c = ldg_cs_ll2(e2 + 2);
        longlong2 d = ldg_cs_ll2(e2 + 3);
        u0 = (int)a.x; v0 = (int)a.y; u1 = (int)b.x; v1 = (int)b.y;
        u2 = (int)c.x; v2 = (int)c.y; u3 = (int)d.x; v3 = (int)d.y;
    }

    // Issue all 8 gathers before consuming any (max MLP).
    float2 hu0 = __ldg(&x[u0]);
    float2 hv0 = __ldg(&x[v0]);
    float2 hu1 = __ldg(&x[u1]);
    float2 hv1 = __ldg(&x[v1]);
    float2 hu2 = __ldg(&x[u2]);
    float2 hv2 = __ldg(&x[v2]);
    float2 hu3 = __ldg(&x[u3]);
    float2 hv3 = __ldg(&x[v3]);

    // t_u = R(+p) h_u -> out[v],  t_v = R(-p) h_v -> out[u]
    float a0 = fmaf(hu0.x, c0, -hu0.y * s0), b0 = fmaf(hu0.x, s0, hu0.y * c0);
    float d0 = fmaf(hv0.x, c0,  hv0.y * s0), e0 = fmaf(hv0.y, c0, -hv0.x * s0);
    float a1 = fmaf(hu1.x, c1, -hu1.y * s1), b1 = fmaf(hu1.x, s1, hu1.y * c1);
    float d1 = fmaf(hv1.x, c1,  hv1.y * s1), e1 = fmaf(hv1.y, c1, -hv1.x * s1);
    float a2 = fmaf(hu2.x, c2, -hu2.y * s2), b2 = fmaf(hu2.x, s2, hu2.y * c2);
    float d2 = fmaf(hv2.x, c2,  hv2.y * s2), e2 = fmaf(hv2.y, c2, -hv2.x * s2);
    float a3 = fmaf(hu3.x, c3, -hu3.y * s3), b3 = fmaf(hu3.x, s3, hu3.y * c3);
    float d3 = fmaf(hv3.x, c3,  hv3.y * s3), e3 = fmaf(hv3.y, c3, -hv3.x * s3);

    red_v2(out + 2 * v0, a0, b0);
    red_v2(out + 2 * u0, d0, e0);
    red_v2(out + 2 * v1, a1, b1);
    red_v2(out + 2 * u1, d1, e1);
    red_v2(out + 2 * v2, a2, b2);
    red_v2(out + 2 * u2, d2, e2);
    red_v2(out + 2 * v3, a3, b3);
    red_v2(out + 2 * u3, d3, e3);
}

extern "C" void kernel_launch(void* const* d_in, const int* in_sizes, int n_in,
                              void* d_out, int out_size) {
    const float* x      = nullptr;
    const float* phases = nullptr;
    const void*  edges  = nullptr;
    for (int i = 0; i < n_in; i++) {
        if      (in_sizes[i] == 2 * N_NODES) x      = (const float*)d_in[i];
        else if (in_sizes[i] == N_EDGES)     phases = (const float*)d_in[i];
        else if (in_sizes[i] == 2 * N_EDGES) edges  = d_in[i];
    }
    float* out = (float*)d_out;

    int n4 = (N_NODES * 2) / 4;  // 500,000
    init_out_kernel<<<(n4 + 255) / 256, 256>>>((const float4*)x, (float4*)out, n4);

    int threads = N_EDGES / 4;                  // 4,000,000
    edge_scatter_kernel<<<threads / 256, 256>>>((const float2*)x, phases, edges, out);
}

// round 5
// speedup vs baseline: 1.0260x; 1.0260x over previous
#include <cuda_runtime.h>
#include <cstdint>

// Inputs (bound by element count, not position):
//   x       float32 [1000000, 2]        -> 2,000,000 elems
//   phases  float32 [16000000]          -> 16,000,000 elems
//   edges   int64-or-int32 [16000000,2] -> 32,000,000 elems
// Output: float32 [1000000, 2]

static constexpr int N_NODES = 1000000;
static constexpr int N_EDGES = 16000000;

// ---------------------------------------------------------------------------
// out = x (out arrives poisoned). 500,000 float4.
// ---------------------------------------------------------------------------
__global__ void init_out_kernel(const float4* __restrict__ x4,
                                float4* __restrict__ out4,
                                int n4) {
    int i = blockIdx.x * blockDim.x + threadIdx.x;
    if (i < n4) out4[i] = x4[i];
}

// ---------------------------------------------------------------------------
// Streaming loads: evict-first (.cs) to keep x/out hot in L2.
// ---------------------------------------------------------------------------
__device__ __forceinline__ int4 ldg_cs_int4(const int4* p) {
    int4 r;
    asm volatile("ld.global.cs.v4.s32 {%0,%1,%2,%3}, [%4];"
                 : "=r"(r.x), "=r"(r.y), "=r"(r.z), "=r"(r.w) : "l"(p));
    return r;
}
__device__ __forceinline__ float2 ldg_cs_float2(const float2* p) {
    float2 r;
    asm volatile("ld.global.cs.v2.f32 {%0,%1}, [%2];"
                 : "=f"(r.x), "=f"(r.y) : "l"(p));
    return r;
}
__device__ __forceinline__ longlong2 ldg_cs_ll2(const longlong2* p) {
    longlong2 r;
    asm volatile("ld.global.cs.v2.s64 {%0,%1}, [%2];"
                 : "=l"(r.x), "=l"(r.y) : "l"(p));
    return r;
}

__device__ __forceinline__ void rotate_scatter(float2 hu, float2 hv,
                                               float s, float c,
                                               float* du, float* dv) {
    // t_u = R(+p) h_u -> out[v],  t_v = R(-p) h_v -> out[u]
    float tu0 = fmaf(hu.x, c, -hu.y * s);
    float tu1 = fmaf(hu.x, s,  hu.y * c);
    float tv0 = fmaf(hv.x, c,  hv.y * s);
    float tv1 = fmaf(hv.y, c, -hv.x * s);
    asm volatile("red.global.add.v2.f32 [%0], {%1, %2};"
                 :: "l"(dv), "f"(tu0), "f"(tu1) : "memory");
    asm volatile("red.global.add.v2.f32 [%0], {%1, %2};"
                 :: "l"(du), "f"(tv0), "f"(tv1) : "memory");
}

// ---------------------------------------------------------------------------
// 2 edges per thread (best-known config), 512-thread blocks.
// All 4 gathers issued before any FMA/red; reds interleaved per edge.
// Edge dtype detected in-kernel from the int64 view (genuine int64 indices
// are < 1e6; int32 pairs misread as int64 are ~4e15).
// ---------------------------------------------------------------------------
__global__ void __launch_bounds__(512)
edge_scatter_kernel(const float2* __restrict__ x,
                    const float* __restrict__ phases,
                    const void* __restrict__ edges_raw,
                    float* __restrict__ out) {
    __shared__ int s_mode;  // 1 = int32 pairs, 2 = int64 pairs
    if (threadIdx.x == 0) {
        const long long* e64 = (const long long*)edges_raw;
        int mode = 2;
        #pragma unroll
        for (int i = 1; i < 9; i += 2) {
            long long val = __ldg(&e64[i]);
            if (val < 0 || val >= (long long)N_NODES) { mode = 1; break; }
        }
        s_mode = mode;
    }
    __syncthreads();
    int mode = s_mode;

    int gid = blockIdx.x * blockDim.x + threadIdx.x;   // [0, N_EDGES/2)
    if (gid >= N_EDGES / 2) return;

    float2 ph = ldg_cs_float2(((const float2*)phases) + gid);
    float s0, c0, s1, c1;
    __sincosf(ph.x, &s0, &c0);
    __sincosf(ph.y, &s1, &c1);

    if (mode == 1) {
        int4 e = ldg_cs_int4(((const int4*)edges_raw) + gid);  // u0,v0,u1,v1
        float2 hu0 = __ldg(&x[e.x]);
        float2 hv0 = __ldg(&x[e.y]);
        float2 hu1 = __ldg(&x[e.z]);
        float2 hv1 = __ldg(&x[e.w]);
        rotate_scatter(hu0, hv0, s0, c0, out + 2 * e.x, out + 2 * e.y);
        rotate_scatter(hu1, hv1, s1, c1, out + 2 * e.z, out + 2 * e.w);
    } else {
        longlong2 e0 = ldg_cs_ll2(((const longlong2*)edges_raw) + 2 * gid);
        longlong2 e1 = ldg_cs_ll2(((const longlong2*)edges_raw) + 2 * gid + 1);
        float2 hu0 = __ldg(&x[e0.x]);
        float2 hv0 = __ldg(&x[e0.y]);
        float2 hu1 = __ldg(&x[e1.x]);
        float2 hv1 = __ldg(&x[e1.y]);
        rotate_scatter(hu0, hv0, s0, c0, out + 2 * e0.x, out + 2 * e0.y);
        rotate_scatter(hu1, hv1, s1, c1, out + 2 * e1.x, out + 2 * e1.y);
    }
}

extern "C" void kernel_launch(void* const* d_in, const int* in_sizes, int n_in,
                              void* d_out, int out_size) {
    const float* x      = nullptr;
    const float* phases = nullptr;
    const void*  edges  = nullptr;
    for (int i = 0; i < n_in; i++) {
        if      (in_sizes[i] == 2 * N_NODES) x      = (const float*)d_in[i];
        else if (in_sizes[i] == N_EDGES)     phases = (const float*)d_in[i];
        else if (in_sizes[i] == 2 * N_EDGES) edges  = d_in[i];
    }
    float* out = (float*)d_out;

    int n4 = (N_NODES * 2) / 4;  // 500,000
    init_out_kernel<<<(n4 + 255) / 256, 256>>>((const float4*)x, (float4*)out, n4);

    int threads = N_EDGES / 2;                  // 8,000,000
    edge_scatter_kernel<<<threads / 512, 512>>>((const float2*)x, phases, edges, out);
}